// round 5
// baseline (speedup 1.0000x reference)
#include <cuda_runtime.h>
#include <cstdint>

// ---------------------------------------------------------------------------
// Problem constants
// ---------------------------------------------------------------------------
#define ORIG_IN   4096
#define ORIG_OUT  4096
#define ACTIVE    2048
#define RANK      16
#define SCALING   2.0f
#define M_TOK     8192          // 2 * 4096 tokens

// Scratch (device globals: allocation-free per harness rules)
__device__ float g_Wp[ACTIVE * ACTIVE];           // folded weight [o][a], tf32-rounded
__device__ float g_xsel[(size_t)M_TOK * ACTIVE];  // gathered x   [n][a], tf32-rounded

// ---------------------------------------------------------------------------
// Helpers
// ---------------------------------------------------------------------------
__device__ __forceinline__ uint32_t smem_u32(const void* p) {
    uint32_t a;
    asm("{ .reg .u64 t; cvta.to.shared.u64 t, %1; cvt.u32.u64 %0, t; }" : "=r"(a) : "l"(p));
    return a;
}
__device__ __forceinline__ float to_tf32(float v) {
    uint32_t t;
    asm("cvt.rna.tf32.f32 %0, %1;" : "=r"(t) : "f"(v));
    return __uint_as_float(t);
}
__device__ __forceinline__ void cp_async16(uint32_t dst, const float* src) {
    asm volatile("cp.async.cg.shared.global [%0], [%1], 16;" :: "r"(dst), "l"(src));
}
#define CP_COMMIT() asm volatile("cp.async.commit_group;" ::: "memory")
#define CP_WAIT2()  asm volatile("cp.async.wait_group 2;" ::: "memory")

__device__ __forceinline__ float lds_f32(uint32_t addr) {
    float v;
    asm volatile("ld.shared.f32 %0, [%1];" : "=f"(v) : "r"(addr));
    return v;
}

__device__ __forceinline__ void mma_tf32(float c[4], const float a[4], const float b[2]) {
    asm volatile(
        "mma.sync.aligned.m16n8k8.row.col.f32.tf32.tf32.f32 "
        "{%0,%1,%2,%3}, {%4,%5,%6,%7}, {%8,%9}, {%0,%1,%2,%3};\n"
        : "+f"(c[0]), "+f"(c[1]), "+f"(c[2]), "+f"(c[3])
        : "r"(__float_as_uint(a[0])), "r"(__float_as_uint(a[1])),
          "r"(__float_as_uint(a[2])), "r"(__float_as_uint(a[3])),
          "r"(__float_as_uint(b[0])), "r"(__float_as_uint(b[1])));
}

// ---------------------------------------------------------------------------
// Kernel 1: fold LoRA into base weight. Wp[o][a] = W[o][a] + 2*sum_r B[o][r]*A[r][a]
// ---------------------------------------------------------------------------
__global__ void fold_kernel(const float* __restrict__ W,
                            const float* __restrict__ lA,
                            const float* __restrict__ lB) {
    int a = blockIdx.x * 256 + threadIdx.x;
    int o = blockIdx.y;
    float acc = W[(size_t)o * ACTIVE + a];
#pragma unroll
    for (int r = 0; r < RANK; r++)
        acc += SCALING * lB[o * RANK + r] * lA[r * ACTIVE + a];
    g_Wp[(size_t)o * ACTIVE + a] = to_tf32(acc);
}

// ---------------------------------------------------------------------------
// Kernel 2: gather selected input columns. xsel[n][a] = x[n][in_idx[a]]
// ---------------------------------------------------------------------------
__global__ void gather_kernel(const float* __restrict__ x,
                              const int* __restrict__ in_idx) {
    int a = blockIdx.x * 256 + threadIdx.x;
    int n = blockIdx.y;
    float v = x[(size_t)n * ORIG_IN + in_idx[a]];
    g_xsel[(size_t)n * ACTIVE + a] = to_tf32(v);
}

// ---------------------------------------------------------------------------
// Kernel 3: zero the full output (harness poisons it with 0xAA)
// ---------------------------------------------------------------------------
__global__ void zero_kernel(float4* __restrict__ out, int n4) {
    int i = blockIdx.x * blockDim.x + threadIdx.x;
    if (i < n4) out[i] = make_float4(0.f, 0.f, 0.f, 0.f);
}

// ---------------------------------------------------------------------------
// Kernel 4: pipelined mma.sync TF32 GEMM.  C[n][o] = sum_a xsel[n][a]*Wp[o][a]
//   CTA tile 256x128, BK=32, 4-stage cp.async ring, 512 threads (16 warps 4x4),
//   warp tile 64x32, conflict-free XOR-swizzled smem, ONE barrier per chunk.
//   Epilogue: out[n*4096 + out_idx[o]] = C + bias[o]
// ---------------------------------------------------------------------------
#define BM 256
#define BN 128
#define BKF 32                       // K floats per chunk (128 B rows)
#define NCHUNK (ACTIVE / BKF)        // 64
#define NSTAGE 4
#define A_BYTES (BM * BKF * 4)       // 32768
#define STAGE_BYTES ((BM + BN) * BKF * 4)   // 49152
#define GEMM_SMEM (NSTAGE * STAGE_BYTES)    // 196608
#define NLD 6                        // cp.async 16B chunks per thread per stage

// smem swizzle: element (row, colFloat) -> row*128 + ((colFloat*4) ^ ((row&7)*16))

__global__ __launch_bounds__(512, 1)
void gemm_mma_kernel(const float* __restrict__ bias,
                     const int* __restrict__ out_idx,
                     float* __restrict__ out) {
    extern __shared__ char smem[];
    const uint32_t sbase = smem_u32(smem);
    const int tid  = threadIdx.x;
    const int lane = tid & 31;
    const int wid  = tid >> 5;
    const int wm   = wid & 3;            // 0..3 -> m offset wm*64
    const int wn   = wid >> 2;           // 0..3 -> n offset wn*32
    const int g    = lane >> 2;          // 0..7
    const int t    = lane & 3;           // 0..3
    const int bm   = blockIdx.y;         // 0..31
    const int bn   = blockIdx.x;         // 0..15

    // ---- per-thread cp.async assignments (6 16B chunks per stage) ----
    const float* __restrict__ Ag = g_xsel + (size_t)(bm * BM) * ACTIVE;
    const float* __restrict__ Bg = g_Wp   + (size_t)(bn * BN) * ACTIVE;

    const float* gsrc[NLD];              // source for k-chunk 0
    uint32_t soff[NLD];                  // swizzled smem byte offset within stage
#pragma unroll
    for (int i = 0; i < NLD; i++) {
        int idx = tid + i * 512;         // 0..3071
        int row = idx >> 3;              // 0..383
        int c   = idx & 7;               // 16B chunk in row
        uint32_t sw = (uint32_t)(((c * 16) ^ ((row & 7) * 16)));
        if (row < BM) {
            gsrc[i] = Ag + (size_t)row * ACTIVE + c * 4;
            soff[i] = (uint32_t)(row * 128) + sw;
        } else {
            int r = row - BM;
            gsrc[i] = Bg + (size_t)r * ACTIVE + c * 4;
            soff[i] = A_BYTES + (uint32_t)(r * 128) + sw;
        }
    }

    // ---- fragment address bases ----
    uint32_t xk[4];
#pragma unroll
    for (int ks = 0; ks < 4; ks++)
        xk[ks] = (uint32_t)((ks * 32 + t * 4) ^ (g * 16));
    uint32_t aRow[4], bRow[4];
#pragma unroll
    for (int mt = 0; mt < 4; mt++) aRow[mt] = (uint32_t)((wm * 64 + mt * 16 + g) * 128);
#pragma unroll
    for (int nt = 0; nt < 4; nt++) bRow[nt] = (uint32_t)(A_BYTES + (wn * 32 + nt * 8 + g) * 128);

    float acc[4][4][4];
#pragma unroll
    for (int mt = 0; mt < 4; mt++)
#pragma unroll
        for (int nt = 0; nt < 4; nt++)
#pragma unroll
            for (int r = 0; r < 4; r++) acc[mt][nt][r] = 0.f;

    // ---- prologue: stages 0..2 ----
#pragma unroll
    for (int s = 0; s < 3; s++) {
#pragma unroll
        for (int i = 0; i < NLD; i++)
            cp_async16(sbase + s * STAGE_BYTES + soff[i], gsrc[i] + s * BKF);
        CP_COMMIT();
    }

    // ---- main loop: ONE barrier per chunk ----
#pragma unroll 1
    for (int c = 0; c < NCHUNK; c++) {
        CP_WAIT2();                      // own groups: chunk c data arrived
        __syncthreads();                 // all threads' chunk-c data visible;
                                         // all reads of chunk c-1 complete

        if (c + 3 < NCHUNK) {            // refill stage (c+3)&3 == (c-1)&3
            const uint32_t sb2 = sbase + ((c + 3) & (NSTAGE - 1)) * STAGE_BYTES;
            const int k0 = (c + 3) * BKF;
#pragma unroll
            for (int i = 0; i < NLD; i++) cp_async16(sb2 + soff[i], gsrc[i] + k0);
        }
        CP_COMMIT();

        const uint32_t sb = sbase + (c & (NSTAGE - 1)) * STAGE_BYTES;
        float fa[4][4], fb[4][2];
#pragma unroll
        for (int ks = 0; ks < 4; ks++) {
#pragma unroll
            for (int mt = 0; mt < 4; mt++) {
                uint32_t a0 = sb + aRow[mt] + xk[ks];
                fa[mt][0] = lds_f32(a0);
                fa[mt][1] = lds_f32(a0 + 1024);
                fa[mt][2] = lds_f32(a0 ^ 16);
                fa[mt][3] = lds_f32((a0 + 1024) ^ 16);
            }
#pragma unroll
            for (int nt = 0; nt < 4; nt++) {
                uint32_t b0 = sb + bRow[nt] + xk[ks];
                fb[nt][0] = lds_f32(b0);
                fb[nt][1] = lds_f32(b0 ^ 16);
            }
#pragma unroll
            for (int mt = 0; mt < 4; mt++)
#pragma unroll
                for (int nt = 0; nt < 4; nt++)
                    mma_tf32(acc[mt][nt], fa[mt], fb[nt]);
        }
    }

    // ---- epilogue: bias + column scatter ----
#pragma unroll
    for (int mt = 0; mt < 4; mt++) {
        const int mrow = bm * BM + wm * 64 + mt * 16 + g;
        float* orow0 = out + (size_t)mrow * ORIG_OUT;
        float* orow1 = out + (size_t)(mrow + 8) * ORIG_OUT;
#pragma unroll
        for (int nt = 0; nt < 4; nt++) {
            const int o0 = bn * BN + wn * 32 + nt * 8 + t * 2;
            const int c0 = __ldg(out_idx + o0);
            const int c1 = __ldg(out_idx + o0 + 1);
            const float b0 = __ldg(bias + o0);
            const float b1 = __ldg(bias + o0 + 1);
            orow0[c0] = acc[mt][nt][0] + b0;
            orow0[c1] = acc[mt][nt][1] + b1;
            orow1[c0] = acc[mt][nt][2] + b0;
            orow1[c1] = acc[mt][nt][3] + b1;
        }
    }
}

// ---------------------------------------------------------------------------
// Launch
// ---------------------------------------------------------------------------
extern "C" void kernel_launch(void* const* d_in, const int* in_sizes, int n_in,
                              void* d_out, int out_size) {
    const float* x      = (const float*)d_in[0];
    const float* W      = (const float*)d_in[1];
    const float* bias   = (const float*)d_in[2];
    const float* lA     = (const float*)d_in[3];
    const float* lB     = (const float*)d_in[4];
    const int* in_idx   = (const int*)d_in[5];
    const int* out_idx  = (const int*)d_in[6];
    float* out          = (float*)d_out;

    static bool attr_set = false;
    if (!attr_set) {
        cudaFuncSetAttribute(gemm_mma_kernel,
                             cudaFuncAttributeMaxDynamicSharedMemorySize, GEMM_SMEM);
        attr_set = true;
    }

    fold_kernel<<<dim3(ACTIVE / 256, ACTIVE), 256>>>(W, lA, lB);
    gather_kernel<<<dim3(ACTIVE / 256, M_TOK), 256>>>(x, in_idx);
    {
        int n4 = out_size / 4;
        zero_kernel<<<(n4 + 255) / 256, 256>>>((float4*)d_out, n4);
    }
    gemm_mma_kernel<<<dim3(ACTIVE / BN, M_TOK / BM), 512, GEMM_SMEM>>>(bias, out_idx, out);
    (void)n_in; (void)in_sizes;
}

// round 7
// speedup vs baseline: 1.0639x; 1.0639x over previous
#include <cuda_runtime.h>
#include <cstdint>

// ---------------------------------------------------------------------------
// Problem constants
// ---------------------------------------------------------------------------
#define ORIG_IN   4096
#define ORIG_OUT  4096
#define ACTIVE    2048
#define RANK      16
#define SCALING   2.0f
#define M_TOK     8192          // 2 * 4096 tokens

// Scratch (device globals: allocation-free per harness rules)
__device__ float g_Wp[ACTIVE * ACTIVE];           // folded weight [o][a], tf32-rounded
__device__ float g_xsel[(size_t)M_TOK * ACTIVE];  // gathered x   [n][a], tf32-rounded

// ---------------------------------------------------------------------------
// Helpers
// ---------------------------------------------------------------------------
__device__ __forceinline__ uint32_t smem_u32(const void* p) {
    uint32_t a;
    asm("{ .reg .u64 t; cvta.to.shared.u64 t, %1; cvt.u32.u64 %0, t; }" : "=r"(a) : "l"(p));
    return a;
}
__device__ __forceinline__ float to_tf32(float v) {
    uint32_t t;
    asm("cvt.rna.tf32.f32 %0, %1;" : "=r"(t) : "f"(v));
    return __uint_as_float(t);
}
__device__ __forceinline__ void cp_async16(uint32_t dst, const float* src) {
    asm volatile("cp.async.cg.shared.global [%0], [%1], 16;" :: "r"(dst), "l"(src));
}
#define CP_COMMIT() asm volatile("cp.async.commit_group;" ::: "memory")
#define CP_WAIT2()  asm volatile("cp.async.wait_group 2;" ::: "memory")

__device__ __forceinline__ float lds_f32(uint32_t addr) {
    float v;
    asm volatile("ld.shared.f32 %0, [%1];" : "=f"(v) : "r"(addr));
    return v;
}

__device__ __forceinline__ void mma_tf32(float c[4], const float a[4], const float b[2]) {
    asm volatile(
        "mma.sync.aligned.m16n8k8.row.col.f32.tf32.tf32.f32 "
        "{%0,%1,%2,%3}, {%4,%5,%6,%7}, {%8,%9}, {%0,%1,%2,%3};\n"
        : "+f"(c[0]), "+f"(c[1]), "+f"(c[2]), "+f"(c[3])
        : "r"(__float_as_uint(a[0])), "r"(__float_as_uint(a[1])),
          "r"(__float_as_uint(a[2])), "r"(__float_as_uint(a[3])),
          "r"(__float_as_uint(b[0])), "r"(__float_as_uint(b[1])));
}

// ---------------------------------------------------------------------------
// Kernel 1: fold LoRA into base weight. Wp[o][a] = W[o][a] + 2*sum_r B[o][r]*A[r][a]
// ---------------------------------------------------------------------------
__global__ void fold_kernel(const float* __restrict__ W,
                            const float* __restrict__ lA,
                            const float* __restrict__ lB) {
    int a = blockIdx.x * 256 + threadIdx.x;
    int o = blockIdx.y;
    float acc = W[(size_t)o * ACTIVE + a];
#pragma unroll
    for (int r = 0; r < RANK; r++)
        acc += SCALING * lB[o * RANK + r] * lA[r * ACTIVE + a];
    g_Wp[(size_t)o * ACTIVE + a] = to_tf32(acc);
}

// ---------------------------------------------------------------------------
// Kernel 2: gather selected input columns. xsel[n][a] = x[n][in_idx[a]]
// ---------------------------------------------------------------------------
__global__ void gather_kernel(const float* __restrict__ x,
                              const int* __restrict__ in_idx) {
    int a = blockIdx.x * 256 + threadIdx.x;
    int n = blockIdx.y;
    float v = x[(size_t)n * ORIG_IN + in_idx[a]];
    g_xsel[(size_t)n * ACTIVE + a] = to_tf32(v);
}

// ---------------------------------------------------------------------------
// Kernel 3: zero the full output (harness poisons it with 0xAA)
// ---------------------------------------------------------------------------
__global__ void zero_kernel(float4* __restrict__ out, int n4) {
    int i = blockIdx.x * blockDim.x + threadIdx.x;
    if (i < n4) out[i] = make_float4(0.f, 0.f, 0.f, 0.f);
}

// ---------------------------------------------------------------------------
// Kernel 4: pipelined mma.sync TF32 GEMM.  C[n][o] = sum_a xsel[n][a]*Wp[o][a]
//   CTA tile 256x128, BK=32, 4-stage cp.async ring, 256 threads (8 warps 4x2),
//   warp tile 64x64 (low smem-crossbar bytes/MAC), XOR-swizzled smem,
//   ONE barrier per chunk.  Epilogue: out[n*4096 + out_idx[o]] = C + bias[o]
// ---------------------------------------------------------------------------
#define BM 256
#define BN 128
#define BKF 32                       // K floats per chunk (128 B rows)
#define NCHUNK (ACTIVE / BKF)        // 64
#define NSTAGE 4
#define A_BYTES (BM * BKF * 4)       // 32768
#define STAGE_BYTES ((BM + BN) * BKF * 4)   // 49152
#define GEMM_SMEM (NSTAGE * STAGE_BYTES)    // 196608
#define NLD 12                       // cp.async 16B chunks per thread per stage

// smem swizzle: element (row, colFloat) -> row*128 + ((colFloat*4) ^ ((row&7)*16))

__global__ __launch_bounds__(256, 1)
void gemm_mma_kernel(const float* __restrict__ bias,
                     const int* __restrict__ out_idx,
                     float* __restrict__ out) {
    extern __shared__ char smem[];
    const uint32_t sbase = smem_u32(smem);
    const int tid  = threadIdx.x;
    const int lane = tid & 31;
    const int wid  = tid >> 5;
    const int wm   = wid & 3;            // 0..3 -> m offset wm*64
    const int wn   = wid >> 2;           // 0..1 -> n offset wn*64
    const int g    = lane >> 2;          // 0..7
    const int t    = lane & 3;           // 0..3
    const int bm   = blockIdx.y;         // 0..31
    const int bn   = blockIdx.x;         // 0..15

    // ---- cp.async assignment: thread covers row0+32*i (A: i<8, B: i>=8) ----
    const int row0 = tid >> 3;           // 0..31
    const int cq   = tid & 7;            // 16B chunk in row
    const uint32_t swx = (uint32_t)((cq * 16) ^ ((row0 & 7) * 16));
    const float* __restrict__ Asrc =
        g_xsel + (size_t)(bm * BM + row0) * ACTIVE + cq * 4;
    const float* __restrict__ Bsrc =
        g_Wp   + (size_t)(bn * BN + row0) * ACTIVE + cq * 4;
    const uint32_t aoff0 = (uint32_t)(row0 * 128) + swx;            // + i*4096
    const uint32_t boff0 = A_BYTES + (uint32_t)(row0 * 128) + swx;  // + i*4096

    // ---- fragment address bases ----
    uint32_t xk[4];
#pragma unroll
    for (int ks = 0; ks < 4; ks++)
        xk[ks] = (uint32_t)((ks * 32 + t * 4) ^ (g * 16));
    uint32_t aRow[4], bRow[8];
#pragma unroll
    for (int mt = 0; mt < 4; mt++) aRow[mt] = (uint32_t)((wm * 64 + mt * 16 + g) * 128);
#pragma unroll
    for (int nt = 0; nt < 8; nt++) bRow[nt] = (uint32_t)(A_BYTES + (wn * 64 + nt * 8 + g) * 128);

    float acc[4][8][4];
#pragma unroll
    for (int mt = 0; mt < 4; mt++)
#pragma unroll
        for (int nt = 0; nt < 8; nt++)
#pragma unroll
            for (int r = 0; r < 4; r++) acc[mt][nt][r] = 0.f;

    // ---- prologue: stages 0..2 ----
#pragma unroll
    for (int s = 0; s < 3; s++) {
        const uint32_t sb = sbase + s * STAGE_BYTES;
        const int k0 = s * BKF;
#pragma unroll
        for (int i = 0; i < 8; i++)
            cp_async16(sb + aoff0 + i * 4096, Asrc + (size_t)i * 32 * ACTIVE + k0);
#pragma unroll
        for (int i = 0; i < 4; i++)
            cp_async16(sb + boff0 + i * 4096, Bsrc + (size_t)i * 32 * ACTIVE + k0);
        CP_COMMIT();
    }

    // ---- main loop: ONE barrier per chunk ----
#pragma unroll 1
    for (int c = 0; c < NCHUNK; c++) {
        CP_WAIT2();
        __syncthreads();

        if (c + 3 < NCHUNK) {            // refill stage (c+3)&3 == (c-1)&3
            const uint32_t sb2 = sbase + ((c + 3) & (NSTAGE - 1)) * STAGE_BYTES;
            const int k0 = (c + 3) * BKF;
#pragma unroll
            for (int i = 0; i < 8; i++)
                cp_async16(sb2 + aoff0 + i * 4096, Asrc + (size_t)i * 32 * ACTIVE + k0);
#pragma unroll
            for (int i = 0; i < 4; i++)
                cp_async16(sb2 + boff0 + i * 4096, Bsrc + (size_t)i * 32 * ACTIVE + k0);
        }
        CP_COMMIT();

        const uint32_t sb = sbase + (c & (NSTAGE - 1)) * STAGE_BYTES;
        float fa[4][4], fb[8][2];
#pragma unroll
        for (int ks = 0; ks < 4; ks++) {
#pragma unroll
            for (int mt = 0; mt < 4; mt++) {
                uint32_t a0 = sb + aRow[mt] + xk[ks];
                fa[mt][0] = lds_f32(a0);
                fa[mt][1] = lds_f32(a0 + 1024);
                fa[mt][2] = lds_f32(a0 ^ 16);
                fa[mt][3] = lds_f32((a0 + 1024) ^ 16);
            }
#pragma unroll
            for (int nt = 0; nt < 8; nt++) {
                uint32_t b0 = sb + bRow[nt] + xk[ks];
                fb[nt][0] = lds_f32(b0);
                fb[nt][1] = lds_f32(b0 ^ 16);
            }
#pragma unroll
            for (int mt = 0; mt < 4; mt++)
#pragma unroll
                for (int nt = 0; nt < 8; nt++)
                    mma_tf32(acc[mt][nt], fa[mt], fb[nt]);
        }
    }

    // ---- epilogue: bias + column scatter ----
#pragma unroll
    for (int mt = 0; mt < 4; mt++) {
        const int mrow = bm * BM + wm * 64 + mt * 16 + g;
        float* orow0 = out + (size_t)mrow * ORIG_OUT;
        float* orow1 = out + (size_t)(mrow + 8) * ORIG_OUT;
#pragma unroll
        for (int nt = 0; nt < 8; nt++) {
            const int o0 = bn * BN + wn * 64 + nt * 8 + t * 2;
            const int c0 = __ldg(out_idx + o0);
            const int c1 = __ldg(out_idx + o0 + 1);
            const float b0 = __ldg(bias + o0);
            const float b1 = __ldg(bias + o0 + 1);
            orow0[c0] = acc[mt][nt][0] + b0;
            orow0[c1] = acc[mt][nt][1] + b1;
            orow1[c0] = acc[mt][nt][2] + b0;
            orow1[c1] = acc[mt][nt][3] + b1;
        }
    }
}

// ---------------------------------------------------------------------------
// Launch
// ---------------------------------------------------------------------------
extern "C" void kernel_launch(void* const* d_in, const int* in_sizes, int n_in,
                              void* d_out, int out_size) {
    const float* x      = (const float*)d_in[0];
    const float* W      = (const float*)d_in[1];
    const float* bias   = (const float*)d_in[2];
    const float* lA     = (const float*)d_in[3];
    const float* lB     = (const float*)d_in[4];
    const int* in_idx   = (const int*)d_in[5];
    const int* out_idx  = (const int*)d_in[6];
    float* out          = (float*)d_out;

    static bool attr_set = false;
    if (!attr_set) {
        cudaFuncSetAttribute(gemm_mma_kernel,
                             cudaFuncAttributeMaxDynamicSharedMemorySize, GEMM_SMEM);
        attr_set = true;
    }

    fold_kernel<<<dim3(ACTIVE / 256, ACTIVE), 256>>>(W, lA, lB);
    gather_kernel<<<dim3(ACTIVE / 256, M_TOK), 256>>>(x, in_idx);
    {
        int n4 = out_size / 4;
        zero_kernel<<<(n4 + 255) / 256, 256>>>((float4*)d_out, n4);
    }
    gemm_mma_kernel<<<dim3(ACTIVE / BN, M_TOK / BM), 256, GEMM_SMEM>>>(bias, out_idx, out);
    (void)n_in; (void)in_sizes;
}

// round 13
// speedup vs baseline: 1.2860x; 1.2088x over previous
#include <cuda_runtime.h>
#include <cstdint>

// ---------------------------------------------------------------------------
// Problem constants
// ---------------------------------------------------------------------------
#define ORIG_IN   4096
#define ORIG_OUT  4096
#define ACTIVE    2048
#define RANK      16
#define SCALING   2.0f
#define M_TOK     8192          // 2 * 4096 tokens

// Scratch (device globals: allocation-free per harness rules)
__device__ float g_Wp[ACTIVE * ACTIVE];           // folded weight [o][a], tf32-rounded
__device__ float g_xsel[(size_t)M_TOK * ACTIVE];  // gathered x   [n][a], tf32-rounded

// ---------------------------------------------------------------------------
// Helpers
// ---------------------------------------------------------------------------
__device__ __forceinline__ uint32_t smem_u32(const void* p) {
    uint32_t a;
    asm("{ .reg .u64 t; cvta.to.shared.u64 t, %1; cvt.u32.u64 %0, t; }" : "=r"(a) : "l"(p));
    return a;
}
__device__ __forceinline__ float to_tf32(float v) {
    uint32_t t;
    asm("cvt.rna.tf32.f32 %0, %1;" : "=r"(t) : "f"(v));
    return __uint_as_float(t);
}
__device__ __forceinline__ void cp_async16(uint32_t dst, const float* src) {
    asm volatile("cp.async.cg.shared.global [%0], [%1], 16;" :: "r"(dst), "l"(src));
}
#define CP_COMMIT() asm volatile("cp.async.commit_group;" ::: "memory")
#define CP_WAIT1()  asm volatile("cp.async.wait_group 1;" ::: "memory")

__device__ __forceinline__ float lds_f32(uint32_t addr) {
    float v;
    asm volatile("ld.shared.f32 %0, [%1];" : "=f"(v) : "r"(addr));
    return v;
}

__device__ __forceinline__ void mma_tf32(float c[4], const float a[4], const float b[2]) {
    asm volatile(
        "mma.sync.aligned.m16n8k8.row.col.f32.tf32.tf32.f32 "
        "{%0,%1,%2,%3}, {%4,%5,%6,%7}, {%8,%9}, {%0,%1,%2,%3};\n"
        : "+f"(c[0]), "+f"(c[1]), "+f"(c[2]), "+f"(c[3])
        : "r"(__float_as_uint(a[0])), "r"(__float_as_uint(a[1])),
          "r"(__float_as_uint(a[2])), "r"(__float_as_uint(a[3])),
          "r"(__float_as_uint(b[0])), "r"(__float_as_uint(b[1])));
}

// ---------------------------------------------------------------------------
// Kernel 1: fold LoRA into base weight. Wp[o][a] = W[o][a] + 2*sum_r B[o][r]*A[r][a]
// ---------------------------------------------------------------------------
__global__ void fold_kernel(const float* __restrict__ W,
                            const float* __restrict__ lA,
                            const float* __restrict__ lB) {
    int a = blockIdx.x * 256 + threadIdx.x;
    int o = blockIdx.y;
    float acc = W[(size_t)o * ACTIVE + a];
#pragma unroll
    for (int r = 0; r < RANK; r++)
        acc += SCALING * lB[o * RANK + r] * lA[r * ACTIVE + a];
    g_Wp[(size_t)o * ACTIVE + a] = to_tf32(acc);
}

// ---------------------------------------------------------------------------
// Kernel 2: gather selected input columns. xsel[n][a] = x[n][in_idx[a]]
// ---------------------------------------------------------------------------
__global__ void gather_kernel(const float* __restrict__ x,
                              const int* __restrict__ in_idx) {
    int a = blockIdx.x * 256 + threadIdx.x;
    int n = blockIdx.y;
    float v = x[(size_t)n * ORIG_IN + in_idx[a]];
    g_xsel[(size_t)n * ACTIVE + a] = to_tf32(v);
}

// ---------------------------------------------------------------------------
// Kernel 3: zero the full output (harness poisons it with 0xAA)
// ---------------------------------------------------------------------------
__global__ void zero_kernel(float4* __restrict__ out, int n4) {
    int i = blockIdx.x * blockDim.x + threadIdx.x;
    if (i < n4) out[i] = make_float4(0.f, 0.f, 0.f, 0.f);
}

// ---------------------------------------------------------------------------
// Kernel 4: pipelined mma.sync TF32 GEMM.  C[n][o] = sum_a xsel[n][a]*Wp[o][a]
//   CTA tile 128x128, 4 warps (2x2) of 64x64, BK=32, 3-stage cp.async ring,
//   96KB smem -> TWO independent CTAs per SM (fills each other's barrier/LDS
//   phases on the tensor pipe).  XOR-swizzled smem, one barrier per chunk.
//   Epilogue: out[n*4096 + out_idx[o]] = C + bias[o]
// ---------------------------------------------------------------------------
#define BM 128
#define BN 128
#define BKF 32                       // K floats per chunk (128 B rows)
#define NCHUNK (ACTIVE / BKF)        // 64
#define NSTAGE 3
#define A_BYTES (BM * BKF * 4)       // 16384
#define STAGE_BYTES ((BM + BN) * BKF * 4)   // 32768
#define GEMM_SMEM (NSTAGE * STAGE_BYTES)    // 98304

// smem swizzle: element (row, colFloat) -> row*128 + ((colFloat*4) ^ ((row&7)*16))

__global__ __launch_bounds__(128, 2)
void gemm_mma_kernel(const float* __restrict__ bias,
                     const int* __restrict__ out_idx,
                     float* __restrict__ out) {
    extern __shared__ char smem[];
    const uint32_t sbase = smem_u32(smem);
    const int tid  = threadIdx.x;
    const int lane = tid & 31;
    const int wid  = tid >> 5;
    const int wm   = wid & 1;            // 0..1 -> m offset wm*64
    const int wn   = wid >> 1;           // 0..1 -> n offset wn*64
    const int g    = lane >> 2;          // 0..7
    const int t    = lane & 3;           // 0..3
    const int bm   = blockIdx.y;         // 0..63
    const int bn   = blockIdx.x;         // 0..15

    // ---- cp.async assignment: 16 chunks/thread: i<8 -> A rows, i>=8 -> B rows ----
    const int row0 = tid >> 3;           // 0..15
    const int cq   = tid & 7;            // 16B chunk in row
    const uint32_t swx = (uint32_t)((cq * 16) ^ ((row0 & 7) * 16));
    const float* __restrict__ Asrc =
        g_xsel + (size_t)(bm * BM + row0) * ACTIVE + cq * 4;
    const float* __restrict__ Bsrc =
        g_Wp   + (size_t)(bn * BN + row0) * ACTIVE + cq * 4;
    const uint32_t aoff0 = (uint32_t)(row0 * 128) + swx;            // + i*2048
    const uint32_t boff0 = A_BYTES + (uint32_t)(row0 * 128) + swx;  // + i*2048

    // ---- fragment address bases ----
    uint32_t xk[4];
#pragma unroll
    for (int ks = 0; ks < 4; ks++)
        xk[ks] = (uint32_t)((ks * 32 + t * 4) ^ (g * 16));
    uint32_t aRow[4], bRow[8];
#pragma unroll
    for (int mt = 0; mt < 4; mt++) aRow[mt] = (uint32_t)((wm * 64 + mt * 16 + g) * 128);
#pragma unroll
    for (int nt = 0; nt < 8; nt++) bRow[nt] = (uint32_t)(A_BYTES + (wn * 64 + nt * 8 + g) * 128);

    float acc[4][8][4];
#pragma unroll
    for (int mt = 0; mt < 4; mt++)
#pragma unroll
        for (int nt = 0; nt < 8; nt++)
#pragma unroll
            for (int r = 0; r < 4; r++) acc[mt][nt][r] = 0.f;

    // ---- prologue: stages 0..1 ----
#pragma unroll
    for (int s = 0; s < 2; s++) {
        const uint32_t sb = sbase + s * STAGE_BYTES;
        const int k0 = s * BKF;
#pragma unroll
        for (int i = 0; i < 8; i++)
            cp_async16(sb + aoff0 + i * 2048, Asrc + (size_t)i * 16 * ACTIVE + k0);
#pragma unroll
        for (int i = 0; i < 8; i++)
            cp_async16(sb + boff0 + i * 2048, Bsrc + (size_t)i * 16 * ACTIVE + k0);
        CP_COMMIT();
    }

    // ---- main loop: ONE barrier per chunk, 3-stage ring ----
    int stage = 0;
#pragma unroll 1
    for (int c = 0; c < NCHUNK; c++) {
        CP_WAIT1();                      // chunk c data arrived
        __syncthreads();                 // visible to all; reads of c-1 done

        if (c + 2 < NCHUNK) {            // refill stage (c+2)%3 == (c-1)%3
            int s2 = stage + 2; if (s2 >= NSTAGE) s2 -= NSTAGE;
            const uint32_t sb2 = sbase + s2 * STAGE_BYTES;
            const int k0 = (c + 2) * BKF;
#pragma unroll
            for (int i = 0; i < 8; i++)
                cp_async16(sb2 + aoff0 + i * 2048, Asrc + (size_t)i * 16 * ACTIVE + k0);
#pragma unroll
            for (int i = 0; i < 8; i++)
                cp_async16(sb2 + boff0 + i * 2048, Bsrc + (size_t)i * 16 * ACTIVE + k0);
        }
        CP_COMMIT();

        const uint32_t sb = sbase + stage * STAGE_BYTES;
        float fa[4][4], fb[8][2];
#pragma unroll
        for (int ks = 0; ks < 4; ks++) {
#pragma unroll
            for (int mt = 0; mt < 4; mt++) {
                uint32_t a0 = sb + aRow[mt] + xk[ks];
                fa[mt][0] = lds_f32(a0);
                fa[mt][1] = lds_f32(a0 + 1024);
                fa[mt][2] = lds_f32(a0 ^ 16);
                fa[mt][3] = lds_f32((a0 + 1024) ^ 16);
            }
#pragma unroll
            for (int nt = 0; nt < 8; nt++) {
                uint32_t b0 = sb + bRow[nt] + xk[ks];
                fb[nt][0] = lds_f32(b0);
                fb[nt][1] = lds_f32(b0 ^ 16);
            }
#pragma unroll
            for (int mt = 0; mt < 4; mt++)
#pragma unroll
                for (int nt = 0; nt < 8; nt++)
                    mma_tf32(acc[mt][nt], fa[mt], fb[nt]);
        }
        stage++; if (stage >= NSTAGE) stage = 0;
    }

    // ---- epilogue: bias + column scatter ----
#pragma unroll
    for (int mt = 0; mt < 4; mt++) {
        const int mrow = bm * BM + wm * 64 + mt * 16 + g;
        float* orow0 = out + (size_t)mrow * ORIG_OUT;
        float* orow1 = out + (size_t)(mrow + 8) * ORIG_OUT;
#pragma unroll
        for (int nt = 0; nt < 8; nt++) {
            const int o0 = bn * BN + wn * 64 + nt * 8 + t * 2;
            const int c0 = __ldg(out_idx + o0);
            const int c1 = __ldg(out_idx + o0 + 1);
            const float b0 = __ldg(bias + o0);
            const float b1 = __ldg(bias + o0 + 1);
            orow0[c0] = acc[mt][nt][0] + b0;
            orow0[c1] = acc[mt][nt][1] + b1;
            orow1[c0] = acc[mt][nt][2] + b0;
            orow1[c1] = acc[mt][nt][3] + b1;
        }
    }
}

// ---------------------------------------------------------------------------
// Launch
// ---------------------------------------------------------------------------
extern "C" void kernel_launch(void* const* d_in, const int* in_sizes, int n_in,
                              void* d_out, int out_size) {
    const float* x      = (const float*)d_in[0];
    const float* W      = (const float*)d_in[1];
    const float* bias   = (const float*)d_in[2];
    const float* lA     = (const float*)d_in[3];
    const float* lB     = (const float*)d_in[4];
    const int* in_idx   = (const int*)d_in[5];
    const int* out_idx  = (const int*)d_in[6];
    float* out          = (float*)d_out;

    static bool attr_set = false;
    if (!attr_set) {
        cudaFuncSetAttribute(gemm_mma_kernel,
                             cudaFuncAttributeMaxDynamicSharedMemorySize, GEMM_SMEM);
        attr_set = true;
    }

    fold_kernel<<<dim3(ACTIVE / 256, ACTIVE), 256>>>(W, lA, lB);
    gather_kernel<<<dim3(ACTIVE / 256, M_TOK), 256>>>(x, in_idx);
    {
        int n4 = out_size / 4;
        zero_kernel<<<(n4 + 255) / 256, 256>>>((float4*)d_out, n4);
    }
    gemm_mma_kernel<<<dim3(ACTIVE / BN, M_TOK / BM), 128, GEMM_SMEM>>>(bias, out_idx, out);
    (void)n_in; (void)in_sizes;
}